// round 1
// baseline (speedup 1.0000x reference)
#include <cuda_runtime.h>
#include <math.h>

#define NN    50000
#define NE    300000
#define INDIM 2000
#define DF    128
#define H1D   256
#define H2D   128
#define ODIM  32
#define KD    4

// ---------------- scratch (static device globals; no allocation) ----------------
static __device__ float d_h0[NN * DF];          // 25.6 MB
static __device__ float d_h1[NN * H1D];         // 51.2 MB
static __device__ float d_z1[KD * NN * H1D];    // 204.8 MB
static __device__ float d_h2[KD * NN * H2D];    // 102.4 MB
static __device__ float d_deg[KD * NN];
static __device__ float d_dinv[KD * NN];
static __device__ float d_norm[KD * NE];        // per-k norms in CSR order
static __device__ int   d_rowptr[NN + 1];
static __device__ int   d_fill[NN];             // counts, then scatter cursors
static __device__ int   d_ssrc[NE];             // src sorted by dst (CSR)
static __device__ int   d_bsum[64];
static __device__ float d_macc[KD * H2D];       // sum over nodes of z2 (pre-mean)

// ---------------- init ----------------
__global__ void init_kernel() {
    int i = blockIdx.x * blockDim.x + threadIdx.x;
    if (i < KD * NN)  d_deg[i] = 1.0f;   // self-loop weight 1 pre-added
    if (i < NN)       d_fill[i] = 0;
    if (i < KD * H2D) d_macc[i] = 0.0f;
}

// ---------------- generic fp32 SGEMM: C[M,N] = A[M,K] @ B[K,N] ----------------
// BM=BN=128, BK=8, 256 threads, 8x8 per-thread tile. Requires K%8==0, N%128==0.
__global__ void sgemm_kernel(const float* __restrict__ A,
                             const float* __restrict__ B,
                             float* __restrict__ C, int M, int N, int K) {
    __shared__ __align__(16) float As[8][128];
    __shared__ __align__(16) float Bs[8][128];

    int tid  = threadIdx.x;
    int row0 = blockIdx.y * 128;
    int col0 = blockIdx.x * 128;

    int ar = tid >> 1;          // 0..127
    int ac = (tid & 1) * 4;     // 0 or 4
    int br = tid >> 5;          // 0..7
    int bc = (tid & 31) * 4;    // 0..124
    int tx = tid & 15;
    int ty = tid >> 4;

    float acc[8][8];
#pragma unroll
    for (int i = 0; i < 8; i++)
#pragma unroll
        for (int j = 0; j < 8; j++) acc[i][j] = 0.0f;

    bool aval = (row0 + ar) < M;
    const float* Aptr = A + (size_t)(row0 + ar) * K + ac;
    const float* Bptr = B + (size_t)br * N + col0 + bc;

    for (int k0 = 0; k0 < K; k0 += 8) {
        float4 av = aval ? *(const float4*)(Aptr + k0) : make_float4(0.f, 0.f, 0.f, 0.f);
        float4 bv = *(const float4*)(Bptr + (size_t)k0 * N);
        As[ac + 0][ar] = av.x;
        As[ac + 1][ar] = av.y;
        As[ac + 2][ar] = av.z;
        As[ac + 3][ar] = av.w;
        *(float4*)&Bs[br][bc] = bv;
        __syncthreads();
#pragma unroll
        for (int kk = 0; kk < 8; kk++) {
            float a[8], b[8];
#pragma unroll
            for (int i = 0; i < 8; i++) a[i] = As[kk][ty * 8 + i];
#pragma unroll
            for (int j = 0; j < 8; j++) b[j] = Bs[kk][tx * 8 + j];
#pragma unroll
            for (int i = 0; i < 8; i++)
#pragma unroll
                for (int j = 0; j < 8; j++) acc[i][j] = fmaf(a[i], b[j], acc[i][j]);
        }
        __syncthreads();
    }

#pragma unroll
    for (int i = 0; i < 8; i++) {
        int r = row0 + ty * 8 + i;
        if (r < M) {
            float* cp = C + (size_t)r * N + col0 + tx * 8;
            *(float4*)cp       = make_float4(acc[i][0], acc[i][1], acc[i][2], acc[i][3]);
            *(float4*)(cp + 4) = make_float4(acc[i][4], acc[i][5], acc[i][6], acc[i][7]);
        }
    }
}

// ---------------- per-edge MLP -> Gk [K,E] (warp per edge) ----------------
__global__ void edge_mlp_kernel(const int* __restrict__ src, const int* __restrict__ dst,
                                const float* __restrict__ W1, const float* __restrict__ b1,
                                const float* __restrict__ W2, const float* __restrict__ b2,
                                float* __restrict__ G) {
    __shared__ float sW1[KD * 2 * DF * 2];  // 2048
    for (int i = threadIdx.x; i < KD * 2 * DF * 2; i += blockDim.x) sW1[i] = W1[i];
    __syncthreads();

    int gid = blockIdx.x * blockDim.x + threadIdx.x;
    int e = gid >> 5;
    int l = threadIdx.x & 31;
    if (e >= NE) return;

    int s = src[e];
    int d = dst[e];

    float acc[8];
#pragma unroll
    for (int q = 0; q < 8; q++) acc[q] = 0.0f;

#pragma unroll
    for (int j = 0; j < 4; j++) {
        int f = l + 32 * j;                   // 0..127
        float xs = d_h0[s * DF + f];
        float xd = d_h0[d * DF + f];
#pragma unroll
        for (int k = 0; k < KD; k++) {
#pragma unroll
            for (int h = 0; h < 2; h++) {
                acc[k * 2 + h] += xs * sW1[(k * 256 + f) * 2 + h]
                                + xd * sW1[(k * 256 + 128 + f) * 2 + h];
            }
        }
    }
#pragma unroll
    for (int q = 0; q < 8; q++) {
#pragma unroll
        for (int off = 16; off > 0; off >>= 1)
            acc[q] += __shfl_xor_sync(0xffffffffu, acc[q], off);
    }
    if (l < KD) {
        int k = l;
        float h0v = fmaxf(acc[k * 2 + 0] + b1[k * 2 + 0], 0.0f);
        float h1v = fmaxf(acc[k * 2 + 1] + b1[k * 2 + 1], 0.0f);
        float logit = h0v * W2[k * 2 + 0] + h1v * W2[k * 2 + 1] + b2[k];
        G[k * NE + e] = 1.0f / (1.0f + expf(-logit));
    }
}

// ---------------- degree accumulation + dst counts ----------------
__global__ void deg_count_kernel(const int* __restrict__ dst, const float* __restrict__ G) {
    int e = blockIdx.x * blockDim.x + threadIdx.x;
    if (e >= NE) return;
    int d = dst[e];
    atomicAdd(&d_fill[d], 1);
#pragma unroll
    for (int k = 0; k < KD; k++) atomicAdd(&d_deg[k * NN + d], G[k * NE + e]);
}

__global__ void dinv_kernel() {
    int i = blockIdx.x * blockDim.x + threadIdx.x;
    if (i < KD * NN) d_dinv[i] = rsqrtf(d_deg[i]);  // deg >= 1 always (self-loop)
}

// ---------------- exclusive scan of counts -> rowptr ----------------
__global__ void scanA_kernel() {
    __shared__ int s[1024];
    int t = threadIdx.x;
    int i = blockIdx.x * 1024 + t;
    int x = (i < NN) ? d_fill[i] : 0;
    s[t] = x;
    __syncthreads();
    for (int off = 1; off < 1024; off <<= 1) {
        int v = (t >= off) ? s[t - off] : 0;
        __syncthreads();
        s[t] += v;
        __syncthreads();
    }
    if (i < NN) d_rowptr[i] = s[t] - x;           // block-local exclusive
    if (t == 1023) d_bsum[blockIdx.x] = s[1023];  // block total
}

__global__ void scanB_kernel(int nblk) {
    if (threadIdx.x == 0 && blockIdx.x == 0) {
        int run = 0;
        for (int b = 0; b < nblk; b++) { int v = d_bsum[b]; d_bsum[b] = run; run += v; }
        d_rowptr[NN] = run;
    }
}

__global__ void scanC_kernel() {
    int i = blockIdx.x * blockDim.x + threadIdx.x;
    if (i < NN) {
        int r = d_rowptr[i] + d_bsum[i >> 10];
        d_rowptr[i] = r;
        d_fill[i] = r;  // scatter cursor
    }
}

// ---------------- scatter into CSR + per-k norms ----------------
__global__ void scatter_kernel(const int* __restrict__ src, const int* __restrict__ dst,
                               const float* __restrict__ G) {
    int e = blockIdx.x * blockDim.x + threadIdx.x;
    if (e >= NE) return;
    int d = dst[e];
    int s = src[e];
    int pos = atomicAdd(&d_fill[d], 1);
    d_ssrc[pos] = s;
#pragma unroll
    for (int k = 0; k < KD; k++)
        d_norm[k * NE + pos] = d_dinv[k * NN + s] * G[k * NE + e] * d_dinv[k * NN + d];
}

// ---------------- GCN layer-1 aggregation (warp per node, all K fused) ----------------
__global__ void agg1_kernel(const float* __restrict__ g1_b) {
    int w = threadIdx.x >> 5, l = threadIdx.x & 31;
    int n = blockIdx.x * 8 + w;
    if (n >= NN) return;

    float acc[KD][8];
#pragma unroll
    for (int k = 0; k < KD; k++)
#pragma unroll
        for (int j = 0; j < 8; j++) acc[k][j] = 0.0f;

    int beg = d_rowptr[n], end = d_rowptr[n + 1];
    for (int i = beg; i < end; i++) {
        int s = d_ssrc[i];
        const float4* hp = (const float4*)(d_h1 + (size_t)s * H1D);
        float4 v0 = hp[l * 2], v1 = hp[l * 2 + 1];
#pragma unroll
        for (int k = 0; k < KD; k++) {
            float wg = d_norm[k * NE + i];
            acc[k][0] = fmaf(wg, v0.x, acc[k][0]);
            acc[k][1] = fmaf(wg, v0.y, acc[k][1]);
            acc[k][2] = fmaf(wg, v0.z, acc[k][2]);
            acc[k][3] = fmaf(wg, v0.w, acc[k][3]);
            acc[k][4] = fmaf(wg, v1.x, acc[k][4]);
            acc[k][5] = fmaf(wg, v1.y, acc[k][5]);
            acc[k][6] = fmaf(wg, v1.z, acc[k][6]);
            acc[k][7] = fmaf(wg, v1.w, acc[k][7]);
        }
    }
    {   // self loop: weight = dinv^2
        const float4* hp = (const float4*)(d_h1 + (size_t)n * H1D);
        float4 v0 = hp[l * 2], v1 = hp[l * 2 + 1];
#pragma unroll
        for (int k = 0; k < KD; k++) {
            float dv = d_dinv[k * NN + n];
            float wg = dv * dv;
            acc[k][0] = fmaf(wg, v0.x, acc[k][0]);
            acc[k][1] = fmaf(wg, v0.y, acc[k][1]);
            acc[k][2] = fmaf(wg, v0.z, acc[k][2]);
            acc[k][3] = fmaf(wg, v0.w, acc[k][3]);
            acc[k][4] = fmaf(wg, v1.x, acc[k][4]);
            acc[k][5] = fmaf(wg, v1.y, acc[k][5]);
            acc[k][6] = fmaf(wg, v1.z, acc[k][6]);
            acc[k][7] = fmaf(wg, v1.w, acc[k][7]);
        }
    }
    float4 b0 = ((const float4*)g1_b)[l * 2];
    float4 b1 = ((const float4*)g1_b)[l * 2 + 1];
#pragma unroll
    for (int k = 0; k < KD; k++) {
        float* zp = d_z1 + ((size_t)(k * NN + n)) * H1D + l * 8;
        *(float4*)zp = make_float4(fmaxf(acc[k][0] + b0.x, 0.f), fmaxf(acc[k][1] + b0.y, 0.f),
                                   fmaxf(acc[k][2] + b0.z, 0.f), fmaxf(acc[k][3] + b0.w, 0.f));
        *(float4*)(zp + 4) = make_float4(fmaxf(acc[k][4] + b1.x, 0.f), fmaxf(acc[k][5] + b1.y, 0.f),
                                         fmaxf(acc[k][6] + b1.z, 0.f), fmaxf(acc[k][7] + b1.w, 0.f));
    }
}

// ---------------- GCN layer-2 aggregation + relu + mean accumulation ----------------
__global__ void agg2_kernel(const float* __restrict__ g2_b) {
    __shared__ float sacc[KD * H2D];
    int t = threadIdx.x;
    for (int i = t; i < KD * H2D; i += 256) sacc[i] = 0.0f;
    __syncthreads();

    int w = t >> 5, l = t & 31;
    int n = blockIdx.x * 8 + w;
    if (n < NN) {
        float acc[KD][4];
#pragma unroll
        for (int k = 0; k < KD; k++)
#pragma unroll
            for (int j = 0; j < 4; j++) acc[k][j] = 0.0f;

        int beg = d_rowptr[n], end = d_rowptr[n + 1];
        for (int i = beg; i < end; i++) {
            int s = d_ssrc[i];
#pragma unroll
            for (int k = 0; k < KD; k++) {
                float wg = d_norm[k * NE + i];
                float4 v = *(const float4*)(d_h2 + ((size_t)(k * NN + s)) * H2D + l * 4);
                acc[k][0] = fmaf(wg, v.x, acc[k][0]);
                acc[k][1] = fmaf(wg, v.y, acc[k][1]);
                acc[k][2] = fmaf(wg, v.z, acc[k][2]);
                acc[k][3] = fmaf(wg, v.w, acc[k][3]);
            }
        }
#pragma unroll
        for (int k = 0; k < KD; k++) {
            float dv = d_dinv[k * NN + n];
            float wg = dv * dv;
            float4 v = *(const float4*)(d_h2 + ((size_t)(k * NN + n)) * H2D + l * 4);
            acc[k][0] = fmaf(wg, v.x, acc[k][0]);
            acc[k][1] = fmaf(wg, v.y, acc[k][1]);
            acc[k][2] = fmaf(wg, v.z, acc[k][2]);
            acc[k][3] = fmaf(wg, v.w, acc[k][3]);
        }
        float4 b = ((const float4*)g2_b)[l];
#pragma unroll
        for (int k = 0; k < KD; k++) {
            atomicAdd(&sacc[k * H2D + l * 4 + 0], fmaxf(acc[k][0] + b.x, 0.f));
            atomicAdd(&sacc[k * H2D + l * 4 + 1], fmaxf(acc[k][1] + b.y, 0.f));
            atomicAdd(&sacc[k * H2D + l * 4 + 2], fmaxf(acc[k][2] + b.z, 0.f));
            atomicAdd(&sacc[k * H2D + l * 4 + 3], fmaxf(acc[k][3] + b.w, 0.f));
        }
    }
    __syncthreads();
    for (int i = t; i < KD * H2D; i += 256) atomicAdd(&d_macc[i], sacc[i]);
}

// ---------------- final descriptors ----------------
__global__ void final_kernel(const float* __restrict__ fc_W, const float* __restrict__ fc_b,
                             float* __restrict__ out) {
    int t = threadIdx.x;  // 128 threads
    int k = t >> 5, o = t & 31;
    const float inv = 1.0f / (float)NN;
    float s = fc_b[o];
    for (int d = 0; d < H2D; d++) s = fmaf(d_macc[k * H2D + d] * inv, fc_W[d * ODIM + o], s);
    out[t] = s;
}

// ---------------- launch ----------------
static float* symf(const void* s) {
    void* p = nullptr;
    cudaGetSymbolAddress(&p, s);
    return (float*)p;
}

extern "C" void kernel_launch(void* const* d_in, const int* in_sizes, int n_in,
                              void* d_out, int out_size) {
    const float* X     = (const float*)d_in[0];
    const int*   ei    = (const int*)d_in[1];
    const float* Wh    = (const float*)d_in[2];
    const float* W1    = (const float*)d_in[3];
    const float* b1    = (const float*)d_in[4];
    const float* W2    = (const float*)d_in[5];
    const float* b2    = (const float*)d_in[6];
    const float* g1_W  = (const float*)d_in[7];
    const float* g1_b  = (const float*)d_in[8];
    const float* g2_W  = (const float*)d_in[9];
    const float* g2_b  = (const float*)d_in[10];
    const float* fc_W  = (const float*)d_in[11];
    const float* fc_b  = (const float*)d_in[12];

    const int* src = ei;
    const int* dst = ei + NE;

    float* out = (float*)d_out;
    float* G   = out + KD * ODIM;   // Gk lives directly in the output buffer

    float* p_h0 = symf(d_h0);
    float* p_h1 = symf(d_h1);
    float* p_z1 = symf(d_z1);
    float* p_h2 = symf(d_h2);

    // 0. init
    init_kernel<<<(KD * NN + 255) / 256, 256>>>();

    // 1. h0 = X @ Wh
    {
        dim3 grid(DF / 128, (NN + 127) / 128);
        sgemm_kernel<<<grid, 256>>>(X, Wh, p_h0, NN, DF, INDIM);
    }

    // 2. Gk
    edge_mlp_kernel<<<NE / 8, 256>>>(src, dst, W1, b1, W2, b2, G);

    // 3. degrees + counts
    deg_count_kernel<<<(NE + 255) / 256, 256>>>(dst, G);
    dinv_kernel<<<(KD * NN + 255) / 256, 256>>>();

    // 4. scan -> rowptr
    int nblk = (NN + 1023) / 1024;  // 49
    scanA_kernel<<<nblk, 1024>>>();
    scanB_kernel<<<1, 32>>>(nblk);
    scanC_kernel<<<(NN + 255) / 256, 256>>>();

    // 5. scatter CSR + norms
    scatter_kernel<<<(NE + 255) / 256, 256>>>(src, dst, G);

    // 6. h1 = h0 @ g1_W
    {
        dim3 grid(H1D / 128, (NN + 127) / 128);
        sgemm_kernel<<<grid, 256>>>(p_h0, g1_W, p_h1, NN, H1D, DF);
    }

    // 7. layer-1 aggregation -> z1 (bias + relu fused, all K)
    agg1_kernel<<<(NN + 7) / 8, 256>>>(g1_b);

    // 8. h2 = z1 @ g2_W  (batched over K: M = K*NN)
    {
        dim3 grid(H2D / 128, (KD * NN + 127) / 128);
        sgemm_kernel<<<grid, 256>>>(p_z1, g2_W, p_h2, KD * NN, H2D, H1D);
    }

    // 9. layer-2 aggregation + relu + mean accumulation
    agg2_kernel<<<(NN + 7) / 8, 256>>>(g2_b);

    // 10. descriptors
    final_kernel<<<1, 128>>>(fc_W, fc_b, out);
}

// round 3
// speedup vs baseline: 2.5608x; 2.5608x over previous
#include <cuda_runtime.h>
#include <cuda_fp16.h>
#include <math.h>
#include <stdint.h>

#define NN    50000
#define NE    300000
#define INDIM 2000
#define DF    128
#define H1D   256
#define H2D   128
#define ODIM  32
#define KD    4
#define KPAD1 2048

// ---------------- scratch (static device globals; no allocation) ----------------
static __device__ __half d_h0[NN * DF];                 // 12.8 MB
static __device__ __half d_h1[NN * H1D];                // 25.6 MB (L2-resident)
static __device__ __half d_z1[KD * NN * H1D];           // 102.4 MB
static __device__ __half d_h2[KD * NN * H2D];           // 51.2 MB
static __device__ __half d_WhT[DF * KPAD1];             // Wh^T fp16 [128, 2048] zero-padded K
static __device__ __half d_g1T[H1D * DF];               // g1_W^T fp16 [256,128]
static __device__ __half d_g2T[H2D * H1D];              // g2_W^T fp16 [128,256]
static __device__ float d_deg[KD * NN];
static __device__ float d_dinv[KD * NN];
static __device__ float d_norm[KD * NE];
static __device__ int   d_rowptr[NN + 1];
static __device__ int   d_fill[NN];
static __device__ int   d_ssrc[NE];
static __device__ int   d_bsum[64];
static __device__ float d_macc[KD * H2D];

__device__ __forceinline__ uint32_t h2u(__half2 h) { return *reinterpret_cast<uint32_t*>(&h); }

__device__ __forceinline__ void mma16816(float* d, const uint32_t* a, const uint32_t* b) {
    asm volatile("mma.sync.aligned.m16n8k16.row.col.f32.f16.f16.f32 "
                 "{%0,%1,%2,%3}, {%4,%5,%6,%7}, {%8,%9}, {%0,%1,%2,%3};"
                 : "+f"(d[0]), "+f"(d[1]), "+f"(d[2]), "+f"(d[3])
                 : "r"(a[0]), "r"(a[1]), "r"(a[2]), "r"(a[3]), "r"(b[0]), "r"(b[1]));
}

// ---------------- HMMA fp16 GEMM: C[M,Ntot](f16) = A[M,Kreal] @ Bt[Ntot,KB]^T ----------
// Block tile 128x128, BK=32, 8 warps (4m x 2n), warp tile 32x64.
// A fp32 (converted in-kernel, col-guarded to Kreal) if AF32, else fp16 (Kreal % 32 == 0).
#define ASTR 40   // smem row stride in halves (conflict-free for fragment loads)

template <bool AF32>
__global__ void __launch_bounds__(256) gemm_hmma(const void* __restrict__ Ain,
                                                 const __half* __restrict__ Bt,
                                                 __half* __restrict__ C,
                                                 int M, int Kreal, int KB, int Ntot, int NC) {
    __shared__ __half As[2][128 * ASTR];
    __shared__ __half Bs[2][128 * ASTR];

    const int tid = threadIdx.x, lane = tid & 31, w = tid >> 5;
    const int wm = w & 3, wn = w >> 2;          // warp grid 4x2
    const int g = lane >> 2, tg = lane & 3;
    const int m0 = blockIdx.x * 128;
    const int n0 = blockIdx.y * 128;

    const int lrow = tid >> 1;                  // 0..127
    const int lcg  = (tid & 1) * 16;            // 0 or 16 (halves)

    float acc[2][8][4];
#pragma unroll
    for (int i = 0; i < 2; i++)
#pragma unroll
        for (int j = 0; j < 8; j++)
#pragma unroll
            for (int q = 0; q < 4; q++) acc[i][j][q] = 0.0f;

    uint32_t ra[8];       // staged A (16 halves)
    uint4    rb[2];       // staged B (16 halves)

    auto ldA = [&](int c) {
        if (AF32) {
            const float* A = (const float*)Ain;
            int grow = m0 + lrow;
            const float* base = A + (size_t)grow * Kreal + c * 32 + lcg;
            bool rok = grow < M;
#pragma unroll
            for (int q = 0; q < 4; q++) {
                int col = c * 32 + lcg + q * 4;
                float4 v = (rok && col < Kreal) ? *(const float4*)(base + q * 4)
                                                : make_float4(0.f, 0.f, 0.f, 0.f);
                ra[q * 2 + 0] = h2u(__floats2half2_rn(v.x, v.y));
                ra[q * 2 + 1] = h2u(__floats2half2_rn(v.z, v.w));
            }
        } else {
            const __half* A = (const __half*)Ain;
            int grow = m0 + lrow;
            bool rok = grow < M;
            const __half* base = A + (size_t)grow * Kreal + c * 32 + lcg;
#pragma unroll
            for (int q = 0; q < 2; q++) {
                uint4 v = rok ? *(const uint4*)(base + q * 8) : make_uint4(0u, 0u, 0u, 0u);
                ra[q * 4 + 0] = v.x; ra[q * 4 + 1] = v.y;
                ra[q * 4 + 2] = v.z; ra[q * 4 + 3] = v.w;
            }
        }
        const __half* bbase = Bt + (size_t)(n0 + lrow) * KB + c * 32 + lcg;
        rb[0] = *(const uint4*)(bbase);
        rb[1] = *(const uint4*)(bbase + 8);
    };

    auto stAB = [&](int buf) {
        __half* ap = &As[buf][lrow * ASTR + lcg];
        ((uint4*)ap)[0] = make_uint4(ra[0], ra[1], ra[2], ra[3]);
        ((uint4*)ap)[1] = make_uint4(ra[4], ra[5], ra[6], ra[7]);
        __half* bp = &Bs[buf][lrow * ASTR + lcg];
        ((uint4*)bp)[0] = rb[0];
        ((uint4*)bp)[1] = rb[1];
    };

    auto compute = [&](int buf) {
#pragma unroll
        for (int ks = 0; ks < 32; ks += 16) {
            uint32_t af[2][4], bf[8][2];
#pragma unroll
            for (int mt = 0; mt < 2; mt++) {
                int r0 = wm * 32 + mt * 16 + g;
                const __half* p0 = &As[buf][r0 * ASTR + ks + tg * 2];
                const __half* p1 = &As[buf][(r0 + 8) * ASTR + ks + tg * 2];
                af[mt][0] = *(const uint32_t*)p0;
                af[mt][1] = *(const uint32_t*)p1;
                af[mt][2] = *(const uint32_t*)(p0 + 8);
                af[mt][3] = *(const uint32_t*)(p1 + 8);
            }
#pragma unroll
            for (int nt = 0; nt < 8; nt++) {
                int nr = wn * 64 + nt * 8 + g;
                const __half* p = &Bs[buf][nr * ASTR + ks + tg * 2];
                bf[nt][0] = *(const uint32_t*)p;
                bf[nt][1] = *(const uint32_t*)(p + 8);
            }
#pragma unroll
            for (int mt = 0; mt < 2; mt++)
#pragma unroll
                for (int nt = 0; nt < 8; nt++)
                    mma16816(acc[mt][nt], af[mt], bf[nt]);
        }
    };

    ldA(0);
    stAB(0);
    __syncthreads();

    for (int c = 0; c < NC; c++) {
        int buf = c & 1;
        if (c + 1 < NC) ldA(c + 1);
        compute(buf);
        if (c + 1 < NC) {
            __syncthreads();
            stAB(buf ^ 1);
            __syncthreads();
        }
    }

    // epilogue: fp32 acc -> fp16 C
#pragma unroll
    for (int mt = 0; mt < 2; mt++) {
        int r1 = m0 + wm * 32 + mt * 16 + g;
        int r2 = r1 + 8;
#pragma unroll
        for (int nt = 0; nt < 8; nt++) {
            int col = n0 + wn * 64 + nt * 8 + tg * 2;
            if (r1 < M)
                *(uint32_t*)(C + (size_t)r1 * Ntot + col) = h2u(__floats2half2_rn(acc[mt][nt][0], acc[mt][nt][1]));
            if (r2 < M)
                *(uint32_t*)(C + (size_t)r2 * Ntot + col) = h2u(__floats2half2_rn(acc[mt][nt][2], acc[mt][nt][3]));
        }
    }
}

// ---------------- weight prep: transpose + fp16 + pad ----------------
__global__ void prep_weights(const float* __restrict__ Wh, const float* __restrict__ g1W,
                             const float* __restrict__ g2W) {
    int i = blockIdx.x * blockDim.x + threadIdx.x;
    if (i < DF * KPAD1) {
        int n = i / KPAD1, k = i % KPAD1;
        d_WhT[i] = (k < INDIM) ? __float2half(Wh[k * DF + n]) : __half(0.f);
    }
    if (i < H1D * DF) {
        int n = i / DF, k = i % DF;
        d_g1T[i] = __float2half(g1W[k * H1D + n]);
    }
    if (i < H2D * H1D) {
        int n = i / H1D, k = i % H1D;
        d_g2T[i] = __float2half(g2W[k * H2D + n]);
    }
}

// ---------------- init ----------------
__global__ void init_kernel() {
    int i = blockIdx.x * blockDim.x + threadIdx.x;
    if (i < KD * NN)  d_deg[i] = 1.0f;
    if (i < NN)       d_fill[i] = 0;
    if (i < KD * H2D) d_macc[i] = 0.0f;
}

// ---------------- per-edge MLP -> Gk [K,E] (warp per edge, h0 fp16) ----------------
__global__ void edge_mlp_kernel(const int* __restrict__ src, const int* __restrict__ dst,
                                const float* __restrict__ W1, const float* __restrict__ b1,
                                const float* __restrict__ W2, const float* __restrict__ b2,
                                float* __restrict__ G) {
    __shared__ float sW1[KD * 2 * DF * 2];
    for (int i = threadIdx.x; i < KD * 2 * DF * 2; i += blockDim.x) sW1[i] = W1[i];
    __syncthreads();

    int gid = blockIdx.x * blockDim.x + threadIdx.x;
    int e = gid >> 5;
    int l = threadIdx.x & 31;
    if (e >= NE) return;

    int s = src[e];
    int d = dst[e];
    const __half2* hs = (const __half2*)d_h0 + (size_t)s * (DF / 2);
    const __half2* hd = (const __half2*)d_h0 + (size_t)d * (DF / 2);

    float acc[8];
#pragma unroll
    for (int q = 0; q < 8; q++) acc[q] = 0.0f;

#pragma unroll
    for (int j = 0; j < 2; j++) {
        int idx = l + 32 * j;
        float2 xs = __half22float2(hs[idx]);
        float2 xd = __half22float2(hd[idx]);
        int f = idx * 2;
#pragma unroll
        for (int k = 0; k < KD; k++) {
#pragma unroll
            for (int h = 0; h < 2; h++) {
                acc[k * 2 + h] += xs.x * sW1[(k * 256 + f) * 2 + h]
                                + xs.y * sW1[(k * 256 + f + 1) * 2 + h]
                                + xd.x * sW1[(k * 256 + 128 + f) * 2 + h]
                                + xd.y * sW1[(k * 256 + 128 + f + 1) * 2 + h];
            }
        }
    }
#pragma unroll
    for (int q = 0; q < 8; q++) {
#pragma unroll
        for (int off = 16; off > 0; off >>= 1)
            acc[q] += __shfl_xor_sync(0xffffffffu, acc[q], off);
    }
    if (l < KD) {
        int k = l;
        float h0v = fmaxf(acc[k * 2 + 0] + b1[k * 2 + 0], 0.0f);
        float h1v = fmaxf(acc[k * 2 + 1] + b1[k * 2 + 1], 0.0f);
        float logit = h0v * W2[k * 2 + 0] + h1v * W2[k * 2 + 1] + b2[k];
        G[k * NE + e] = 1.0f / (1.0f + expf(-logit));
    }
}

// ---------------- degree accumulation + dst counts ----------------
__global__ void deg_count_kernel(const int* __restrict__ dst, const float* __restrict__ G) {
    int e = blockIdx.x * blockDim.x + threadIdx.x;
    if (e >= NE) return;
    int d = dst[e];
    atomicAdd(&d_fill[d], 1);
#pragma unroll
    for (int k = 0; k < KD; k++) atomicAdd(&d_deg[k * NN + d], G[k * NE + e]);
}

__global__ void dinv_kernel() {
    int i = blockIdx.x * blockDim.x + threadIdx.x;
    if (i < KD * NN) d_dinv[i] = rsqrtf(d_deg[i]);
}

// ---------------- scan -> rowptr ----------------
__global__ void scanA_kernel() {
    __shared__ int s[1024];
    int t = threadIdx.x;
    int i = blockIdx.x * 1024 + t;
    int x = (i < NN) ? d_fill[i] : 0;
    s[t] = x;
    __syncthreads();
    for (int off = 1; off < 1024; off <<= 1) {
        int v = (t >= off) ? s[t - off] : 0;
        __syncthreads();
        s[t] += v;
        __syncthreads();
    }
    if (i < NN) d_rowptr[i] = s[t] - x;
    if (t == 1023) d_bsum[blockIdx.x] = s[1023];
}
__global__ void scanB_kernel(int nblk) {
    if (threadIdx.x == 0 && blockIdx.x == 0) {
        int run = 0;
        for (int b = 0; b < nblk; b++) { int v = d_bsum[b]; d_bsum[b] = run; run += v; }
        d_rowptr[NN] = run;
    }
}
__global__ void scanC_kernel() {
    int i = blockIdx.x * blockDim.x + threadIdx.x;
    if (i < NN) {
        int r = d_rowptr[i] + d_bsum[i >> 10];
        d_rowptr[i] = r;
        d_fill[i] = r;
    }
}

// ---------------- scatter into CSR + per-k norms ----------------
__global__ void scatter_kernel(const int* __restrict__ src, const int* __restrict__ dst,
                               const float* __restrict__ G) {
    int e = blockIdx.x * blockDim.x + threadIdx.x;
    if (e >= NE) return;
    int d = dst[e];
    int s = src[e];
    int pos = atomicAdd(&d_fill[d], 1);
    d_ssrc[pos] = s;
#pragma unroll
    for (int k = 0; k < KD; k++)
        d_norm[k * NE + pos] = d_dinv[k * NN + s] * G[k * NE + e] * d_dinv[k * NN + d];
}

// ---------------- GCN layer-1 aggregation (fp16 h1 in, fp16 z1 out) ----------------
__global__ void agg1_kernel(const float* __restrict__ g1_b) {
    int w = threadIdx.x >> 5, l = threadIdx.x & 31;
    int n = blockIdx.x * 8 + w;
    if (n >= NN) return;

    float acc[KD][8];
#pragma unroll
    for (int k = 0; k < KD; k++)
#pragma unroll
        for (int j = 0; j < 8; j++) acc[k][j] = 0.0f;

    int beg = d_rowptr[n], end = d_rowptr[n + 1];
    for (int i = beg; i < end; i++) {
        int s = d_ssrc[i];
        uint4 raw = *((const uint4*)(d_h1 + (size_t)s * H1D) + l);
        __half2* hh = (__half2*)&raw;
        float2 f0 = __half22float2(hh[0]), f1 = __half22float2(hh[1]);
        float2 f2 = __half22float2(hh[2]), f3 = __half22float2(hh[3]);
#pragma unroll
        for (int k = 0; k < KD; k++) {
            float wg = d_norm[k * NE + i];
            acc[k][0] = fmaf(wg, f0.x, acc[k][0]); acc[k][1] = fmaf(wg, f0.y, acc[k][1]);
            acc[k][2] = fmaf(wg, f1.x, acc[k][2]); acc[k][3] = fmaf(wg, f1.y, acc[k][3]);
            acc[k][4] = fmaf(wg, f2.x, acc[k][4]); acc[k][5] = fmaf(wg, f2.y, acc[k][5]);
            acc[k][6] = fmaf(wg, f3.x, acc[k][6]); acc[k][7] = fmaf(wg, f3.y, acc[k][7]);
        }
    }
    {
        uint4 raw = *((const uint4*)(d_h1 + (size_t)n * H1D) + l);
        __half2* hh = (__half2*)&raw;
        float2 f0 = __half22float2(hh[0]), f1 = __half22float2(hh[1]);
        float2 f2 = __half22float2(hh[2]), f3 = __half22float2(hh[3]);
#pragma unroll
        for (int k = 0; k < KD; k++) {
            float dv = d_dinv[k * NN + n];
            float wg = dv * dv;
            acc[k][0] = fmaf(wg, f0.x, acc[k][0]); acc[k][1] = fmaf(wg, f0.y, acc[k][1]);
            acc[k][2] = fmaf(wg, f1.x, acc[k][2]); acc[k][3] = fmaf(wg, f1.y, acc[k][3]);
            acc[k][4] = fmaf(wg, f2.x, acc[k][4]); acc[k][5] = fmaf(wg, f2.y, acc[k][5]);
            acc[k][6] = fmaf(wg, f3.x, acc[k][6]); acc[k][7] = fmaf(wg, f3.y, acc[k][7]);
        }
    }
    float4 b0 = ((const float4*)g1_b)[l * 2];
    float4 b1 = ((const float4*)g1_b)[l * 2 + 1];
#pragma unroll
    for (int k = 0; k < KD; k++) {
        uint32_t p0 = h2u(__floats2half2_rn(fmaxf(acc[k][0] + b0.x, 0.f), fmaxf(acc[k][1] + b0.y, 0.f)));
        uint32_t p1 = h2u(__floats2half2_rn(fmaxf(acc[k][2] + b0.z, 0.f), fmaxf(acc[k][3] + b0.w, 0.f)));
        uint32_t p2 = h2u(__floats2half2_rn(fmaxf(acc[k][4] + b1.x, 0.f), fmaxf(acc[k][5] + b1.y, 0.f)));
        uint32_t p3 = h2u(__floats2half2_rn(fmaxf(acc[k][6] + b1.z, 0.f), fmaxf(acc[k][7] + b1.w, 0.f)));
        *((uint4*)(d_z1 + ((size_t)(k * NN + n)) * H1D) + l) = make_uint4(p0, p1, p2, p3);
    }
}

// ---------------- GCN layer-2 aggregation + relu + mean accumulation (fp16 h2) --------
__global__ void agg2_kernel(const float* __restrict__ g2_b) {
    __shared__ float sacc[KD * H2D];
    int t = threadIdx.x;
    for (int i = t; i < KD * H2D; i += 256) sacc[i] = 0.0f;
    __syncthreads();

    int w = t >> 5, l = t & 31;
    int n = blockIdx.x * 8 + w;
    if (n < NN) {
        float acc[KD][4];
#pragma unroll
        for (int k = 0; k < KD; k++)
#pragma unroll
            for (int j = 0; j < 4; j++) acc[k][j] = 0.0f;

        int beg = d_rowptr[n], end = d_rowptr[n + 1];
        for (int i = beg; i < end; i++) {
            int s = d_ssrc[i];
#pragma unroll
            for (int k = 0; k < KD; k++) {
                float wg = d_norm[k * NE + i];
                uint2 raw = *((const uint2*)(d_h2 + ((size_t)(k * NN + s)) * H2D) + l);
                __half2* hh = (__half2*)&raw;
                float2 f0 = __half22float2(hh[0]), f1 = __half22float2(hh[1]);
                acc[k][0] = fmaf(wg, f0.x, acc[k][0]); acc[k][1] = fmaf(wg, f0.y, acc[k][1]);
                acc[k][2] = fmaf(wg, f1.x, acc[k][2]); acc[k][3] = fmaf(wg, f1.y, acc[k][3]);
            }
        }
#pragma unroll
        for (int k = 0; k < KD; k++) {
            float dv = d_dinv[k * NN + n];
            float wg = dv * dv;
            uint2 raw = *((const uint2*)(d_h2 + ((size_t)(k * NN + n)) * H2D) + l);
            __half2* hh = (__half2*)&raw;
            float2 f0 = __half22float2(hh[0]), f1 = __half22float2(hh[1]);
            acc[k][0] = fmaf(wg, f0.x, acc[k][0]); acc[k][1] = fmaf(wg, f0.y, acc[k][1]);
            acc[k][2] = fmaf(wg, f1.x, acc[k][2]); acc[k][3] = fmaf(wg, f1.y, acc[k][3]);
        }
        float4 b = ((const float4*)g2_b)[l];
#pragma unroll
        for (int k = 0; k < KD; k++) {
            atomicAdd(&sacc[k * H2D + l * 4 + 0], fmaxf(acc[k][0] + b.x, 0.f));
            atomicAdd(&sacc[k * H2D + l * 4 + 1], fmaxf(acc[k][1] + b.y, 0.f));
            atomicAdd(&sacc[k * H2D + l * 4 + 2], fmaxf(acc[k][2] + b.z, 0.f));
            atomicAdd(&sacc[k * H2D + l * 4 + 3], fmaxf(acc[k][3] + b.w, 0.f));
        }
    }
    __syncthreads();
    for (int i = t; i < KD * H2D; i += 256) atomicAdd(&d_macc[i], sacc[i]);
}

// ---------------- final descriptors ----------------
__global__ void final_kernel(const float* __restrict__ fc_W, const float* __restrict__ fc_b,
                             float* __restrict__ out) {
    int t = threadIdx.x;
    int k = t >> 5, o = t & 31;
    const float inv = 1.0f / (float)NN;
    float s = fc_b[o];
    for (int d = 0; d < H2D; d++) s = fmaf(d_macc[k * H2D + d] * inv, fc_W[d * ODIM + o], s);
    out[t] = s;
}

// ---------------- launch ----------------
static void* symp(const void* s) {
    void* p = nullptr;
    cudaGetSymbolAddress(&p, s);
    return p;
}

extern "C" void kernel_launch(void* const* d_in, const int* in_sizes, int n_in,
                              void* d_out, int out_size) {
    const float* X     = (const float*)d_in[0];
    const int*   ei    = (const int*)d_in[1];
    const float* Wh    = (const float*)d_in[2];
    const float* W1    = (const float*)d_in[3];
    const float* b1    = (const float*)d_in[4];
    const float* W2    = (const float*)d_in[5];
    const float* b2    = (const float*)d_in[6];
    const float* g1_W  = (const float*)d_in[7];
    const float* g1_b  = (const float*)d_in[8];
    const float* g2_W  = (const float*)d_in[9];
    const float* g2_b  = (const float*)d_in[10];
    const float* fc_W  = (const float*)d_in[11];
    const float* fc_b  = (const float*)d_in[12];

    const int* src = ei;
    const int* dst = ei + NE;

    float* out = (float*)d_out;
    float* G   = out + KD * ODIM;

    __half* p_h0  = (__half*)symp(d_h0);
    __half* p_h1  = (__half*)symp(d_h1);
    __half* p_z1  = (__half*)symp(d_z1);
    __half* p_h2  = (__half*)symp(d_h2);
    __half* p_WhT = (__half*)symp(d_WhT);
    __half* p_g1T = (__half*)symp(d_g1T);
    __half* p_g2T = (__half*)symp(d_g2T);

    init_kernel<<<(KD * NN + 255) / 256, 256>>>();
    prep_weights<<<(DF * KPAD1 + 255) / 256, 256>>>(Wh, g1_W, g2_W);

    // 1. h0 = fp16(X @ Wh) — HMMA, fp32 A converted in-kernel, K padded to 2048
    {
        dim3 grid((NN + 127) / 128, 1);
        gemm_hmma<true><<<grid, 256>>>(X, p_WhT, p_h0, NN, INDIM, KPAD1, DF, KPAD1 / 32);
    }

    // 2. Gk
    edge_mlp_kernel<<<NE / 8, 256>>>(src, dst, W1, b1, W2, b2, G);

    // 3. degrees + counts
    deg_count_kernel<<<(NE + 255) / 256, 256>>>(dst, G);
    dinv_kernel<<<(KD * NN + 255) / 256, 256>>>();

    // 4. scan -> rowptr
    int nblk = (NN + 1023) / 1024;
    scanA_kernel<<<nblk, 1024>>>();
    scanB_kernel<<<1, 32>>>(nblk);
    scanC_kernel<<<(NN + 255) / 256, 256>>>();

    // 5. scatter CSR + norms
    scatter_kernel<<<(NE + 255) / 256, 256>>>(src, dst, G);

    // 6. h1 = fp16(h0 @ g1_W)
    {
        dim3 grid((NN + 127) / 128, H1D / 128);
        gemm_hmma<false><<<grid, 256>>>(p_h0, p_g1T, p_h1, NN, DF, DF, H1D, DF / 32);
    }

    // 7. layer-1 aggregation -> z1 fp16
    agg1_kernel<<<(NN + 7) / 8, 256>>>(g1_b);

    // 8. h2 = fp16(z1 @ g2_W) (batched over K: M = K*NN)
    {
        dim3 grid((KD * NN + 127) / 128, H2D / 128);
        gemm_hmma<false><<<grid, 256>>>(p_z1, p_g2T, p_h2, KD * NN, H1D, H1D, H2D, H1D / 32);
    }

    // 9. layer-2 aggregation + relu + mean accumulation
    agg2_kernel<<<(NN + 7) / 8, 256>>>(g2_b);

    // 10. descriptors
    final_kernel<<<1, 128>>>(fc_W, fc_b, out);
}

// round 4
// speedup vs baseline: 2.9438x; 1.1496x over previous
#include <cuda_runtime.h>
#include <cuda_fp16.h>
#include <math.h>
#include <stdint.h>

#define NN    50000
#define NE    300000
#define INDIM 2000
#define DF    128
#define H1D   256
#define H2D   128
#define ODIM  32
#define KD    4
#define KPAD1 2048

// ---------------- scratch (static device globals; no allocation) ----------------
static __device__ __half d_h0[NN * DF];                 // 12.8 MB
static __device__ __half d_h1[NN * H1D];                // 25.6 MB (L2-resident)
static __device__ __half d_z1[KD * NN * H1D];           // 102.4 MB
static __device__ __half d_h2[KD * NN * H2D];           // 51.2 MB
static __device__ __half d_pq[NN * 128];                // node projections (16 cols used)
static __device__ __half d_WhT[DF * KPAD1];             // Wh^T fp16 [128, 2048] zero-padded K
static __device__ __half d_g1T[H1D * DF];               // g1_W^T fp16 [256,128]
static __device__ __half d_g2T[H2D * H1D];              // g2_W^T fp16 [128,256]
static __device__ __half d_prjT[128 * DF];              // edge-MLP proj weights^T (16 real rows)
static __device__ float d_deg[KD * NN];
static __device__ float d_dinv[KD * NN];
static __device__ float d_norm[KD * NE];
static __device__ int   d_rowptr[NN + 1];
static __device__ int   d_fill[NN];
static __device__ int   d_ssrc[NE];
static __device__ int   d_bsum[64];
static __device__ float d_macc[KD * H2D];

__device__ __forceinline__ uint32_t h2u(__half2 h) { return *reinterpret_cast<uint32_t*>(&h); }

__device__ __forceinline__ void mma16816(float* d, const uint32_t* a, const uint32_t* b) {
    asm volatile("mma.sync.aligned.m16n8k16.row.col.f32.f16.f16.f32 "
                 "{%0,%1,%2,%3}, {%4,%5,%6,%7}, {%8,%9}, {%0,%1,%2,%3};"
                 : "+f"(d[0]), "+f"(d[1]), "+f"(d[2]), "+f"(d[3])
                 : "r"(a[0]), "r"(a[1]), "r"(a[2]), "r"(a[3]), "r"(b[0]), "r"(b[1]));
}

// ---------------- HMMA fp16 GEMM: C[M,Ntot](f16) = A[M,Kreal] @ Bt[Ntot,KB]^T ----------
// Block tile 128x128, BK=32, 8 warps (4m x 2n), warp tile 32x64.
#define ASTR 40

template <bool AF32>
__global__ void __launch_bounds__(256) gemm_hmma(const void* __restrict__ Ain,
                                                 const __half* __restrict__ Bt,
                                                 __half* __restrict__ C,
                                                 int M, int Kreal, int KB, int Ntot, int NC) {
    __shared__ __half As[2][128 * ASTR];
    __shared__ __half Bs[2][128 * ASTR];

    const int tid = threadIdx.x, lane = tid & 31, w = tid >> 5;
    const int wm = w & 3, wn = w >> 2;
    const int g = lane >> 2, tg = lane & 3;
    const int m0 = blockIdx.x * 128;
    const int n0 = blockIdx.y * 128;

    const int lrow = tid >> 1;
    const int lcg  = (tid & 1) * 16;

    float acc[2][8][4];
#pragma unroll
    for (int i = 0; i < 2; i++)
#pragma unroll
        for (int j = 0; j < 8; j++)
#pragma unroll
            for (int q = 0; q < 4; q++) acc[i][j][q] = 0.0f;

    uint32_t ra[8];
    uint4    rb[2];

    auto ldA = [&](int c) {
        if (AF32) {
            const float* A = (const float*)Ain;
            int grow = m0 + lrow;
            const float* base = A + (size_t)grow * Kreal + c * 32 + lcg;
            bool rok = grow < M;
#pragma unroll
            for (int q = 0; q < 4; q++) {
                int col = c * 32 + lcg + q * 4;
                float4 v = (rok && col < Kreal) ? *(const float4*)(base + q * 4)
                                                : make_float4(0.f, 0.f, 0.f, 0.f);
                ra[q * 2 + 0] = h2u(__floats2half2_rn(v.x, v.y));
                ra[q * 2 + 1] = h2u(__floats2half2_rn(v.z, v.w));
            }
        } else {
            const __half* A = (const __half*)Ain;
            int grow = m0 + lrow;
            bool rok = grow < M;
            const __half* base = A + (size_t)grow * Kreal + c * 32 + lcg;
#pragma unroll
            for (int q = 0; q < 2; q++) {
                uint4 v = rok ? *(const uint4*)(base + q * 8) : make_uint4(0u, 0u, 0u, 0u);
                ra[q * 4 + 0] = v.x; ra[q * 4 + 1] = v.y;
                ra[q * 4 + 2] = v.z; ra[q * 4 + 3] = v.w;
            }
        }
        const __half* bbase = Bt + (size_t)(n0 + lrow) * KB + c * 32 + lcg;
        rb[0] = *(const uint4*)(bbase);
        rb[1] = *(const uint4*)(bbase + 8);
    };

    auto stAB = [&](int buf) {
        __half* ap = &As[buf][lrow * ASTR + lcg];
        ((uint4*)ap)[0] = make_uint4(ra[0], ra[1], ra[2], ra[3]);
        ((uint4*)ap)[1] = make_uint4(ra[4], ra[5], ra[6], ra[7]);
        __half* bp = &Bs[buf][lrow * ASTR + lcg];
        ((uint4*)bp)[0] = rb[0];
        ((uint4*)bp)[1] = rb[1];
    };

    auto compute = [&](int buf) {
#pragma unroll
        for (int ks = 0; ks < 32; ks += 16) {
            uint32_t af[2][4], bf[8][2];
#pragma unroll
            for (int mt = 0; mt < 2; mt++) {
                int r0 = wm * 32 + mt * 16 + g;
                const __half* p0 = &As[buf][r0 * ASTR + ks + tg * 2];
                const __half* p1 = &As[buf][(r0 + 8) * ASTR + ks + tg * 2];
                af[mt][0] = *(const uint32_t*)p0;
                af[mt][1] = *(const uint32_t*)p1;
                af[mt][2] = *(const uint32_t*)(p0 + 8);
                af[mt][3] = *(const uint32_t*)(p1 + 8);
            }
#pragma unroll
            for (int nt = 0; nt < 8; nt++) {
                int nr = wn * 64 + nt * 8 + g;
                const __half* p = &Bs[buf][nr * ASTR + ks + tg * 2];
                bf[nt][0] = *(const uint32_t*)p;
                bf[nt][1] = *(const uint32_t*)(p + 8);
            }
#pragma unroll
            for (int mt = 0; mt < 2; mt++)
#pragma unroll
                for (int nt = 0; nt < 8; nt++)
                    mma16816(acc[mt][nt], af[mt], bf[nt]);
        }
    };

    ldA(0);
    stAB(0);
    __syncthreads();

    for (int c = 0; c < NC; c++) {
        int buf = c & 1;
        if (c + 1 < NC) ldA(c + 1);
        compute(buf);
        if (c + 1 < NC) {
            __syncthreads();
            stAB(buf ^ 1);
            __syncthreads();
        }
    }

#pragma unroll
    for (int mt = 0; mt < 2; mt++) {
        int r1 = m0 + wm * 32 + mt * 16 + g;
        int r2 = r1 + 8;
#pragma unroll
        for (int nt = 0; nt < 8; nt++) {
            int col = n0 + wn * 64 + nt * 8 + tg * 2;
            if (r1 < M)
                *(uint32_t*)(C + (size_t)r1 * Ntot + col) = h2u(__floats2half2_rn(acc[mt][nt][0], acc[mt][nt][1]));
            if (r2 < M)
                *(uint32_t*)(C + (size_t)r2 * Ntot + col) = h2u(__floats2half2_rn(acc[mt][nt][2], acc[mt][nt][3]));
        }
    }
}

// ---------------- weight prep: transpose + fp16 + pad + edge-MLP proj weights ---------
__global__ void prep_weights(const float* __restrict__ Wh, const float* __restrict__ g1W,
                             const float* __restrict__ g2W, const float* __restrict__ W1) {
    int i = blockIdx.x * blockDim.x + threadIdx.x;
    if (i < DF * KPAD1) {
        int n = i / KPAD1, k = i % KPAD1;
        d_WhT[i] = (k < INDIM) ? __float2half(Wh[k * DF + n]) : __half(0.f);
    }
    if (i < H1D * DF) {
        int n = i / DF, k = i % DF;
        d_g1T[i] = __float2half(g1W[k * H1D + n]);
    }
    if (i < H2D * H1D) {
        int n = i / H1D, k = i % H1D;
        d_g2T[i] = __float2half(g2W[k * H2D + n]);
    }
    if (i < 128 * DF) {
        int o = i / DF, f = i % DF;
        float v = 0.0f;
        if (o < 8) {                       // src role: rows f of W1
            int k = o >> 1, h = o & 1;
            v = W1[(k * 256 + f) * 2 + h];
        } else if (o < 16) {               // dst role: rows 128+f
            int o8 = o - 8;
            int k = o8 >> 1, h = o8 & 1;
            v = W1[(k * 256 + 128 + f) * 2 + h];
        }
        d_prjT[i] = __float2half(v);
    }
}

// ---------------- init ----------------
__global__ void init_kernel() {
    int i = blockIdx.x * blockDim.x + threadIdx.x;
    if (i < KD * NN)  d_deg[i] = 1.0f;
    if (i < NN)       d_fill[i] = 0;
    if (i < KD * H2D) d_macc[i] = 0.0f;
}

// ---------------- edge gate: thread/edge, uses per-node projections; fused deg+count --
__global__ void edge_gate_kernel(const int* __restrict__ src, const int* __restrict__ dst,
                                 const float* __restrict__ b1, const float* __restrict__ W2,
                                 const float* __restrict__ b2, float* __restrict__ G) {
    int e = blockIdx.x * blockDim.x + threadIdx.x;
    if (e >= NE) return;
    int s = src[e];
    int d = dst[e];
    uint4 pu = *(const uint4*)(d_pq + (size_t)s * 128);       // p: halves 0..7
    uint4 qu = *(const uint4*)(d_pq + (size_t)d * 128 + 8);   // q: halves 8..15
    const __half2* ph = (const __half2*)&pu;
    const __half2* qh = (const __half2*)&qu;
#pragma unroll
    for (int k = 0; k < KD; k++) {
        float2 pf = __half22float2(ph[k]);
        float2 qf = __half22float2(qh[k]);
        float h0v = fmaxf(pf.x + qf.x + b1[k * 2 + 0], 0.0f);
        float h1v = fmaxf(pf.y + qf.y + b1[k * 2 + 1], 0.0f);
        float logit = h0v * W2[k * 2 + 0] + h1v * W2[k * 2 + 1] + b2[k];
        float gk = 1.0f / (1.0f + expf(-logit));
        G[k * NE + e] = gk;
        atomicAdd(&d_deg[k * NN + d], gk);
    }
    atomicAdd(&d_fill[d], 1);
}

__global__ void dinv_kernel() {
    int i = blockIdx.x * blockDim.x + threadIdx.x;
    if (i < KD * NN) d_dinv[i] = rsqrtf(d_deg[i]);
}

// ---------------- scan -> rowptr ----------------
__global__ void scanA_kernel() {
    __shared__ int s[1024];
    int t = threadIdx.x;
    int i = blockIdx.x * 1024 + t;
    int x = (i < NN) ? d_fill[i] : 0;
    s[t] = x;
    __syncthreads();
    for (int off = 1; off < 1024; off <<= 1) {
        int v = (t >= off) ? s[t - off] : 0;
        __syncthreads();
        s[t] += v;
        __syncthreads();
    }
    if (i < NN) d_rowptr[i] = s[t] - x;
    if (t == 1023) d_bsum[blockIdx.x] = s[1023];
}
__global__ void scanB_kernel(int nblk) {
    if (threadIdx.x == 0 && blockIdx.x == 0) {
        int run = 0;
        for (int b = 0; b < nblk; b++) { int v = d_bsum[b]; d_bsum[b] = run; run += v; }
        d_rowptr[NN] = run;
    }
}
__global__ void scanC_kernel() {
    int i = blockIdx.x * blockDim.x + threadIdx.x;
    if (i < NN) {
        int r = d_rowptr[i] + d_bsum[i >> 10];
        d_rowptr[i] = r;
        d_fill[i] = r;
    }
}

// ---------------- scatter into CSR + per-k norms ----------------
__global__ void scatter_kernel(const int* __restrict__ src, const int* __restrict__ dst,
                               const float* __restrict__ G) {
    int e = blockIdx.x * blockDim.x + threadIdx.x;
    if (e >= NE) return;
    int d = dst[e];
    int s = src[e];
    int pos = atomicAdd(&d_fill[d], 1);
    d_ssrc[pos] = s;
#pragma unroll
    for (int k = 0; k < KD; k++)
        d_norm[k * NE + pos] = d_dinv[k * NN + s] * G[k * NE + e] * d_dinv[k * NN + d];
}

// ---------------- GCN layer-1 aggregation (fp16 h1 in, fp16 z1 out) ----------------
__global__ void agg1_kernel(const float* __restrict__ g1_b) {
    int w = threadIdx.x >> 5, l = threadIdx.x & 31;
    int n = blockIdx.x * 8 + w;
    if (n >= NN) return;

    float acc[KD][8];
#pragma unroll
    for (int k = 0; k < KD; k++)
#pragma unroll
        for (int j = 0; j < 8; j++) acc[k][j] = 0.0f;

    int beg = d_rowptr[n], end = d_rowptr[n + 1];
    for (int i = beg; i < end; i++) {
        int s = d_ssrc[i];
        uint4 raw = *((const uint4*)(d_h1 + (size_t)s * H1D) + l);
        __half2* hh = (__half2*)&raw;
        float2 f0 = __half22float2(hh[0]), f1 = __half22float2(hh[1]);
        float2 f2 = __half22float2(hh[2]), f3 = __half22float2(hh[3]);
#pragma unroll
        for (int k = 0; k < KD; k++) {
            float wg = d_norm[k * NE + i];
            acc[k][0] = fmaf(wg, f0.x, acc[k][0]); acc[k][1] = fmaf(wg, f0.y, acc[k][1]);
            acc[k][2] = fmaf(wg, f1.x, acc[k][2]); acc[k][3] = fmaf(wg, f1.y, acc[k][3]);
            acc[k][4] = fmaf(wg, f2.x, acc[k][4]); acc[k][5] = fmaf(wg, f2.y, acc[k][5]);
            acc[k][6] = fmaf(wg, f3.x, acc[k][6]); acc[k][7] = fmaf(wg, f3.y, acc[k][7]);
        }
    }
    {
        uint4 raw = *((const uint4*)(d_h1 + (size_t)n * H1D) + l);
        __half2* hh = (__half2*)&raw;
        float2 f0 = __half22float2(hh[0]), f1 = __half22float2(hh[1]);
        float2 f2 = __half22float2(hh[2]), f3 = __half22float2(hh[3]);
#pragma unroll
        for (int k = 0; k < KD; k++) {
            float dv = d_dinv[k * NN + n];
            float wg = dv * dv;
            acc[k][0] = fmaf(wg, f0.x, acc[k][0]); acc[k][1] = fmaf(wg, f0.y, acc[k][1]);
            acc[k][2] = fmaf(wg, f1.x, acc[k][2]); acc[k][3] = fmaf(wg, f1.y, acc[k][3]);
            acc[k][4] = fmaf(wg, f2.x, acc[k][4]); acc[k][5] = fmaf(wg, f2.y, acc[k][5]);
            acc[k][6] = fmaf(wg, f3.x, acc[k][6]); acc[k][7] = fmaf(wg, f3.y, acc[k][7]);
        }
    }
    float4 b0 = ((const float4*)g1_b)[l * 2];
    float4 b1 = ((const float4*)g1_b)[l * 2 + 1];
#pragma unroll
    for (int k = 0; k < KD; k++) {
        uint32_t p0 = h2u(__floats2half2_rn(fmaxf(acc[k][0] + b0.x, 0.f), fmaxf(acc[k][1] + b0.y, 0.f)));
        uint32_t p1 = h2u(__floats2half2_rn(fmaxf(acc[k][2] + b0.z, 0.f), fmaxf(acc[k][3] + b0.w, 0.f)));
        uint32_t p2 = h2u(__floats2half2_rn(fmaxf(acc[k][4] + b1.x, 0.f), fmaxf(acc[k][5] + b1.y, 0.f)));
        uint32_t p3 = h2u(__floats2half2_rn(fmaxf(acc[k][6] + b1.z, 0.f), fmaxf(acc[k][7] + b1.w, 0.f)));
        *((uint4*)(d_z1 + ((size_t)(k * NN + n)) * H1D) + l) = make_uint4(p0, p1, p2, p3);
    }
}

// ---------------- GCN layer-2 aggregation (per-k via blockIdx.y) + mean accum ---------
__global__ void agg2_kernel(const float* __restrict__ g2_b) {
    __shared__ float sacc[H2D];
    int t = threadIdx.x;
    int k = blockIdx.y;
    if (t < H2D) sacc[t] = 0.0f;
    __syncthreads();

    int w = t >> 5, l = t & 31;
    int n = blockIdx.x * 8 + w;
    if (n < NN) {
        float a0 = 0.f, a1 = 0.f, a2 = 0.f, a3 = 0.f;
        const __half* h2k = d_h2 + (size_t)k * NN * H2D;
        const float*  nrm = d_norm + (size_t)k * NE;

        int beg = d_rowptr[n], end = d_rowptr[n + 1];
        for (int i = beg; i < end; i++) {
            int s = d_ssrc[i];
            float wg = nrm[i];
            uint2 raw = *((const uint2*)(h2k + (size_t)s * H2D) + l);
            __half2* hh = (__half2*)&raw;
            float2 f0 = __half22float2(hh[0]), f1 = __half22float2(hh[1]);
            a0 = fmaf(wg, f0.x, a0); a1 = fmaf(wg, f0.y, a1);
            a2 = fmaf(wg, f1.x, a2); a3 = fmaf(wg, f1.y, a3);
        }
        {
            float dv = d_dinv[k * NN + n];
            float wg = dv * dv;
            uint2 raw = *((const uint2*)(h2k + (size_t)n * H2D) + l);
            __half2* hh = (__half2*)&raw;
            float2 f0 = __half22float2(hh[0]), f1 = __half22float2(hh[1]);
            a0 = fmaf(wg, f0.x, a0); a1 = fmaf(wg, f0.y, a1);
            a2 = fmaf(wg, f1.x, a2); a3 = fmaf(wg, f1.y, a3);
        }
        float4 b = ((const float4*)g2_b)[l];
        atomicAdd(&sacc[l * 4 + 0], fmaxf(a0 + b.x, 0.f));
        atomicAdd(&sacc[l * 4 + 1], fmaxf(a1 + b.y, 0.f));
        atomicAdd(&sacc[l * 4 + 2], fmaxf(a2 + b.z, 0.f));
        atomicAdd(&sacc[l * 4 + 3], fmaxf(a3 + b.w, 0.f));
    }
    __syncthreads();
    if (t < H2D) atomicAdd(&d_macc[k * H2D + t], sacc[t]);
}

// ---------------- final descriptors ----------------
__global__ void final_kernel(const float* __restrict__ fc_W, const float* __restrict__ fc_b,
                             float* __restrict__ out) {
    int t = threadIdx.x;
    int k = t >> 5, o = t & 31;
    const float inv = 1.0f / (float)NN;
    float s = fc_b[o];
    for (int d = 0; d < H2D; d++) s = fmaf(d_macc[k * H2D + d] * inv, fc_W[d * ODIM + o], s);
    out[t] = s;
}

// ---------------- launch ----------------
static void* symp(const void* s) {
    void* p = nullptr;
    cudaGetSymbolAddress(&p, s);
    return p;
}

extern "C" void kernel_launch(void* const* d_in, const int* in_sizes, int n_in,
                              void* d_out, int out_size) {
    const float* X     = (const float*)d_in[0];
    const int*   ei    = (const int*)d_in[1];
    const float* Wh    = (const float*)d_in[2];
    const float* W1    = (const float*)d_in[3];
    const float* b1    = (const float*)d_in[4];
    const float* W2    = (const float*)d_in[5];
    const float* b2    = (const float*)d_in[6];
    const float* g1_W  = (const float*)d_in[7];
    const float* g1_b  = (const float*)d_in[8];
    const float* g2_W  = (const float*)d_in[9];
    const float* g2_b  = (const float*)d_in[10];
    const float* fc_W  = (const float*)d_in[11];
    const float* fc_b  = (const float*)d_in[12];

    const int* src = ei;
    const int* dst = ei + NE;

    float* out = (float*)d_out;
    float* G   = out + KD * ODIM;

    __half* p_h0   = (__half*)symp(d_h0);
    __half* p_h1   = (__half*)symp(d_h1);
    __half* p_z1   = (__half*)symp(d_z1);
    __half* p_h2   = (__half*)symp(d_h2);
    __half* p_pq   = (__half*)symp(d_pq);
    __half* p_WhT  = (__half*)symp(d_WhT);
    __half* p_g1T  = (__half*)symp(d_g1T);
    __half* p_g2T  = (__half*)symp(d_g2T);
    __half* p_prjT = (__half*)symp(d_prjT);

    init_kernel<<<(KD * NN + 255) / 256, 256>>>();
    prep_weights<<<(DF * KPAD1 + 255) / 256, 256>>>(Wh, g1_W, g2_W, W1);

    // 1. h0 = fp16(X @ Wh) — HMMA, fp32 A converted in-kernel
    {
        dim3 grid((NN + 127) / 128, 1);
        gemm_hmma<true><<<grid, 256>>>(X, p_WhT, p_h0, NN, INDIM, KPAD1, DF, KPAD1 / 32);
    }

    // 1b. per-node edge-MLP projections: pq = h0 @ PrjW^T (16 useful cols of 128)
    {
        dim3 grid((NN + 127) / 128, 1);
        gemm_hmma<false><<<grid, 256>>>(p_h0, p_prjT, p_pq, NN, DF, DF, 128, DF / 32);
    }

    // 2. edge gates + degree accumulation + dst counts (fused)
    edge_gate_kernel<<<(NE + 255) / 256, 256>>>(src, dst, b1, W2, b2, G);

    // 3. dinv
    dinv_kernel<<<(KD * NN + 255) / 256, 256>>>();

    // 4. scan -> rowptr
    int nblk = (NN + 1023) / 1024;
    scanA_kernel<<<nblk, 1024>>>();
    scanB_kernel<<<1, 32>>>(nblk);
    scanC_kernel<<<(NN + 255) / 256, 256>>>();

    // 5. scatter CSR + norms
    scatter_kernel<<<(NE + 255) / 256, 256>>>(src, dst, G);

    // 6. h1 = fp16(h0 @ g1_W)
    {
        dim3 grid((NN + 127) / 128, H1D / 128);
        gemm_hmma<false><<<grid, 256>>>(p_h0, p_g1T, p_h1, NN, DF, DF, H1D, DF / 32);
    }

    // 7. layer-1 aggregation -> z1 fp16
    agg1_kernel<<<(NN + 7) / 8, 256>>>(g1_b);

    // 8. h2 = fp16(z1 @ g2_W) (batched over K: M = K*NN)
    {
        dim3 grid((KD * NN + 127) / 128, H2D / 128);
        gemm_hmma<false><<<grid, 256>>>(p_z1, p_g2T, p_h2, KD * NN, H1D, H1D, H2D, H1D / 32);
    }

    // 9. layer-2 aggregation + relu + mean accumulation (k = blockIdx.y for L2 locality)
    {
        dim3 grid((NN + 7) / 8, KD);
        agg2_kernel<<<grid, 256>>>(g2_b);
    }

    // 10. descriptors
    final_kernel<<<1, 128>>>(fc_W, fc_b, out);
}

// round 7
// speedup vs baseline: 3.5503x; 1.2060x over previous
#include <cuda_runtime.h>
#include <cuda_fp16.h>
#include <math.h>
#include <stdint.h>

#define NN    50000
#define NE    300000
#define INDIM 2000
#define DF    128
#define H1D   256
#define H2D   128
#define ODIM  32
#define KD    4
#define KPAD1 2048

// ---------------- scratch (static device globals; no allocation) ----------------
static __device__ __half d_h0[NN * DF];                 // 12.8 MB
static __device__ __half d_h1[NN * H1D];                // 25.6 MB
static __device__ __half d_z1[KD * NN * H1D];           // 102.4 MB
static __device__ __half d_h2[KD * NN * H2D];           // 51.2 MB
static __device__ float  d_pqf[NN * 16];                // node projections fp32 (3.2 MB)
static __device__ __half d_WhT[DF * KPAD1];             // Wh^T fp16 [128, 2048] zero-padded K
static __device__ __half d_g1T[H1D * DF];               // g1_W^T fp16 [256,128]
static __device__ __half d_g2T[H2D * H1D];              // g2_W^T fp16 [128,256]
static __device__ float d_deg[KD * NN];
static __device__ float d_dinv[KD * NN];
static __device__ float d_norm[KD * NE];
static __device__ int   d_rowptr[NN + 1];
static __device__ int   d_fill[NN];
static __device__ int   d_ssrc[NE];
static __device__ int   d_bsum[64];
static __device__ float d_macc[KD * H2D];

__device__ __forceinline__ uint32_t h2u(__half2 h) { return *reinterpret_cast<uint32_t*>(&h); }

__device__ __forceinline__ uint32_t smem_u32(const void* p) {
    uint32_t a;
    asm("{ .reg .u64 t; cvta.to.shared.u64 t, %1; cvt.u32.u64 %0, t; }" : "=r"(a) : "l"(p));
    return a;
}
__device__ __forceinline__ void cp_async16(uint32_t saddr, const void* gaddr, uint32_t ssize) {
    asm volatile("cp.async.cg.shared.global [%0], [%1], 16, %2;"
                 :: "r"(saddr), "l"(gaddr), "r"(ssize) : "memory");
}
#define CP_COMMIT() asm volatile("cp.async.commit_group;" ::: "memory")
#define CP_WAIT2()  asm volatile("cp.async.wait_group 2;" ::: "memory")

__device__ __forceinline__ void mma16816(float* d, const uint32_t* a, const uint32_t* b) {
    asm volatile("mma.sync.aligned.m16n8k16.row.col.f32.f16.f16.f32 "
                 "{%0,%1,%2,%3}, {%4,%5,%6,%7}, {%8,%9}, {%0,%1,%2,%3};"
                 : "+f"(d[0]), "+f"(d[1]), "+f"(d[2]), "+f"(d[3])
                 : "r"(a[0]), "r"(a[1]), "r"(a[2]), "r"(a[3]), "r"(b[0]), "r"(b[1]));
}

// ---------------- cp.async 4-stage HMMA GEMM: C[M,Ntot](f16) = A @ Bt^T ----------------
// Block tile 128x128, BK=32, 8 warps (4m x 2n), warp tile 32x64, 4 pipeline stages.
#define NSTG 4
template <bool AF32>
__global__ void __launch_bounds__(256) gemm_pipe(const void* __restrict__ Ain,
                                                 const __half* __restrict__ Bt,
                                                 __half* __restrict__ C,
                                                 int M, int Kreal, int KB, int Ntot, int NC) {
    extern __shared__ char sm[];
    const int ASTAGE = AF32 ? (128 * 144) : (128 * 80);
    const int BSTAGE = 128 * 80;
    char* Abase = sm;
    char* Bbase = sm + NSTG * ASTAGE;

    const int tid = threadIdx.x, lane = tid & 31, w = tid >> 5;
    const int wm = w & 3, wn = w >> 2;
    const int g = lane >> 2, tg = lane & 3;
    const int m0 = blockIdx.x * 128;
    const int n0 = blockIdx.y * 128;

    float acc[2][8][4];
#pragma unroll
    for (int i = 0; i < 2; i++)
#pragma unroll
        for (int j = 0; j < 8; j++)
#pragma unroll
            for (int q = 0; q < 4; q++) acc[i][j][q] = 0.0f;

    auto issue_copy = [&](int stage, int c) {
        uint32_t sA = smem_u32(Abase + stage * ASTAGE);
        uint32_t sB = smem_u32(Bbase + stage * BSTAGE);
        if (AF32) {
            const float* A = (const float*)Ain;
#pragma unroll
            for (int t = 0; t < 4; t++) {
                int idx = tid + t * 256;
                int row = idx >> 3, c16 = idx & 7;
                int gr = m0 + row;
                int gcol = c * 32 + c16 * 4;
                uint32_t ok = (gr < M && gcol < Kreal) ? 16u : 0u;
                int grc = (gr < M) ? gr : 0;
                int gcc = (gcol < Kreal) ? gcol : 0;
                cp_async16(sA + row * 144 + c16 * 16, A + (size_t)grc * Kreal + gcc, ok);
            }
        } else {
            const __half* A = (const __half*)Ain;
#pragma unroll
            for (int t = 0; t < 2; t++) {
                int idx = tid + t * 256;
                int row = idx >> 2, c16 = idx & 3;
                int gr = m0 + row;
                uint32_t ok = (gr < M) ? 16u : 0u;
                int grc = (gr < M) ? gr : 0;
                cp_async16(sA + row * 80 + c16 * 16, A + (size_t)grc * Kreal + c * 32 + c16 * 8, ok);
            }
        }
#pragma unroll
        for (int t = 0; t < 2; t++) {
            int idx = tid + t * 256;
            int row = idx >> 2, c16 = idx & 3;
            cp_async16(sB + row * 80 + c16 * 16, Bt + (size_t)(n0 + row) * KB + c * 32 + c16 * 8, 16u);
        }
    };

    auto compute = [&](int stage) {
        char* As = Abase + stage * ASTAGE;
        char* Bs = Bbase + stage * BSTAGE;
#pragma unroll
        for (int ks = 0; ks < 32; ks += 16) {
            uint32_t af[2][4], bf[8][2];
#pragma unroll
            for (int mt = 0; mt < 2; mt++) {
                int r0 = wm * 32 + mt * 16 + g;
                if (AF32) {
                    const float2* pA0 = (const float2*)(As + r0 * 144 + (ks + 2 * tg) * 4);
                    const float2* pA1 = (const float2*)(As + (r0 + 8) * 144 + (ks + 2 * tg) * 4);
                    float2 v0 = pA0[0], v1 = pA1[0], v2 = pA0[4], v3 = pA1[4];
                    af[mt][0] = h2u(__floats2half2_rn(v0.x, v0.y));
                    af[mt][1] = h2u(__floats2half2_rn(v1.x, v1.y));
                    af[mt][2] = h2u(__floats2half2_rn(v2.x, v2.y));
                    af[mt][3] = h2u(__floats2half2_rn(v3.x, v3.y));
                } else {
                    const char* p0 = As + r0 * 80 + (ks + 2 * tg) * 2;
                    const char* p1 = As + (r0 + 8) * 80 + (ks + 2 * tg) * 2;
                    af[mt][0] = *(const uint32_t*)p0;
                    af[mt][1] = *(const uint32_t*)p1;
                    af[mt][2] = *(const uint32_t*)(p0 + 16);
                    af[mt][3] = *(const uint32_t*)(p1 + 16);
                }
            }
#pragma unroll
            for (int nt = 0; nt < 8; nt++) {
                int nr = wn * 64 + nt * 8 + g;
                const char* p = Bs + nr * 80 + (ks + 2 * tg) * 2;
                bf[nt][0] = *(const uint32_t*)p;
                bf[nt][1] = *(const uint32_t*)(p + 16);
            }
#pragma unroll
            for (int mt = 0; mt < 2; mt++)
#pragma unroll
                for (int nt = 0; nt < 8; nt++)
                    mma16816(acc[mt][nt], af[mt], bf[nt]);
        }
    };

    for (int s = 0; s < NSTG - 1; s++) {
        if (s < NC) issue_copy(s, s);
        CP_COMMIT();
    }

    for (int c = 0; c < NC; c++) {
        CP_WAIT2();
        __syncthreads();
        compute(c & (NSTG - 1));
        int cn = c + NSTG - 1;
        if (cn < NC) issue_copy(cn & (NSTG - 1), cn);
        CP_COMMIT();
    }

#pragma unroll
    for (int mt = 0; mt < 2; mt++) {
        int r1 = m0 + wm * 32 + mt * 16 + g;
        int r2 = r1 + 8;
#pragma unroll
        for (int nt = 0; nt < 8; nt++) {
            int col = n0 + wn * 64 + nt * 8 + tg * 2;
            if (r1 < M)
                *(uint32_t*)(C + (size_t)r1 * Ntot + col) = h2u(__floats2half2_rn(acc[mt][nt][0], acc[mt][nt][1]));
            if (r2 < M)
                *(uint32_t*)(C + (size_t)r2 * Ntot + col) = h2u(__floats2half2_rn(acc[mt][nt][2], acc[mt][nt][3]));
        }
    }
}

// ---------------- weight prep ----------------
__global__ void prep_weights(const float* __restrict__ Wh, const float* __restrict__ g1W,
                             const float* __restrict__ g2W) {
    int i = blockIdx.x * blockDim.x + threadIdx.x;
    if (i < DF * KPAD1) {
        int n = i / KPAD1, k = i % KPAD1;
        d_WhT[i] = (k < INDIM) ? __float2half(Wh[k * DF + n]) : __half(0.f);
    }
    if (i < H1D * DF) {
        int n = i / DF, k = i % DF;
        d_g1T[i] = __float2half(g1W[k * H1D + n]);
    }
    if (i < H2D * H1D) {
        int n = i / H1D, k = i % H1D;
        d_g2T[i] = __float2half(g2W[k * H2D + n]);
    }
}

// ---------------- init ----------------
__global__ void init_kernel() {
    int i = blockIdx.x * blockDim.x + threadIdx.x;
    if (i < KD * NN)  d_deg[i] = 1.0f;
    if (i < NN)       d_fill[i] = 0;
    if (i < KD * H2D) d_macc[i] = 0.0f;
}

// ---------------- per-node edge-MLP projections (SIMT, thread per node) --------------
// FIXED: h0 row is 128 halves = 64 uint32 (was 32 -> summed only half the features)
__global__ void pq_kernel(const float* __restrict__ W1) {
    __shared__ float w[DF][16];
    for (int i = threadIdx.x; i < DF * 16; i += 256) {
        int f = i >> 4, o = i & 15;
        float v;
        if (o < 8) { int k = o >> 1, h = o & 1; v = W1[(k * 256 + f) * 2 + h]; }
        else       { int o8 = o - 8; int k = o8 >> 1, h = o8 & 1; v = W1[(k * 256 + 128 + f) * 2 + h]; }
        w[f][o] = v;
    }
    __syncthreads();

    int n = blockIdx.x * 256 + threadIdx.x;
    if (n >= NN) return;
    float acc[16];
#pragma unroll
    for (int o = 0; o < 16; o++) acc[o] = 0.0f;

    const uint32_t* hu = (const uint32_t*)(d_h0 + (size_t)n * DF);
#pragma unroll
    for (int j = 0; j < 64; j++) {
        uint32_t raw = hu[j];
        __half2 hx = *reinterpret_cast<__half2*>(&raw);
        float2 x = __half22float2(hx);
        int f = j * 2;
#pragma unroll
        for (int o = 0; o < 16; o++)
            acc[o] += x.x * w[f][o] + x.y * w[f + 1][o];
    }
    float* outp = d_pqf + (size_t)n * 16;
    *(float4*)(outp + 0)  = make_float4(acc[0], acc[1], acc[2], acc[3]);
    *(float4*)(outp + 4)  = make_float4(acc[4], acc[5], acc[6], acc[7]);
    *(float4*)(outp + 8)  = make_float4(acc[8], acc[9], acc[10], acc[11]);
    *(float4*)(outp + 12) = make_float4(acc[12], acc[13], acc[14], acc[15]);
}

// ---------------- edge gate: thread/edge; fused deg+count ----------------
__global__ void edge_gate_kernel(const int* __restrict__ src, const int* __restrict__ dst,
                                 const float* __restrict__ b1, const float* __restrict__ W2,
                                 const float* __restrict__ b2, float* __restrict__ G) {
    int e = blockIdx.x * blockDim.x + threadIdx.x;
    if (e >= NE) return;
    int s = src[e];
    int d = dst[e];
    float4 p0 = *(const float4*)(d_pqf + (size_t)s * 16);
    float4 p1 = *(const float4*)(d_pqf + (size_t)s * 16 + 4);
    float4 q0 = *(const float4*)(d_pqf + (size_t)d * 16 + 8);
    float4 q1 = *(const float4*)(d_pqf + (size_t)d * 16 + 12);
    float pv[8] = {p0.x, p0.y, p0.z, p0.w, p1.x, p1.y, p1.z, p1.w};
    float qv[8] = {q0.x, q0.y, q0.z, q0.w, q1.x, q1.y, q1.z, q1.w};
#pragma unroll
    for (int k = 0; k < KD; k++) {
        float h0v = fmaxf(pv[k * 2 + 0] + qv[k * 2 + 0] + b1[k * 2 + 0], 0.0f);
        float h1v = fmaxf(pv[k * 2 + 1] + qv[k * 2 + 1] + b1[k * 2 + 1], 0.0f);
        float logit = h0v * W2[k * 2 + 0] + h1v * W2[k * 2 + 1] + b2[k];
        float gk = 1.0f / (1.0f + expf(-logit));
        G[k * NE + e] = gk;
        atomicAdd(&d_deg[k * NN + d], gk);
    }
    atomicAdd(&d_fill[d], 1);
}

__global__ void dinv_kernel() {
    int i = blockIdx.x * blockDim.x + threadIdx.x;
    if (i < KD * NN) d_dinv[i] = rsqrtf(d_deg[i]);
}

// ---------------- scan -> rowptr ----------------
__global__ void scanA_kernel() {
    __shared__ int s[1024];
    int t = threadIdx.x;
    int i = blockIdx.x * 1024 + t;
    int x = (i < NN) ? d_fill[i] : 0;
    s[t] = x;
    __syncthreads();
    for (int off = 1; off < 1024; off <<= 1) {
        int v = (t >= off) ? s[t - off] : 0;
        __syncthreads();
        s[t] += v;
        __syncthreads();
    }
    if (i < NN) d_rowptr[i] = s[t] - x;
    if (t == 1023) d_bsum[blockIdx.x] = s[1023];
}
__global__ void scanB_kernel(int nblk) {
    if (threadIdx.x == 0 && blockIdx.x == 0) {
        int run = 0;
        for (int b = 0; b < nblk; b++) { int v = d_bsum[b]; d_bsum[b] = run; run += v; }
        d_rowptr[NN] = run;
    }
}
__global__ void scanC_kernel() {
    int i = blockIdx.x * blockDim.x + threadIdx.x;
    if (i < NN) {
        int r = d_rowptr[i] + d_bsum[i >> 10];
        d_rowptr[i] = r;
        d_fill[i] = r;
    }
}

// ---------------- scatter into CSR + per-k norms ----------------
__global__ void scatter_kernel(const int* __restrict__ src, const int* __restrict__ dst,
                               const float* __restrict__ G) {
    int e = blockIdx.x * blockDim.x + threadIdx.x;
    if (e >= NE) return;
    int d = dst[e];
    int s = src[e];
    int pos = atomicAdd(&d_fill[d], 1);
    d_ssrc[pos] = s;
#pragma unroll
    for (int k = 0; k < KD; k++)
        d_norm[k * NE + pos] = d_dinv[k * NN + s] * G[k * NE + e] * d_dinv[k * NN + d];
}

// ---------------- GCN layer-1 aggregation (fp16 h1 in, fp16 z1 out) ----------------
__global__ void agg1_kernel(const float* __restrict__ g1_b) {
    int w = threadIdx.x >> 5, l = threadIdx.x & 31;
    int n = blockIdx.x * 8 + w;
    if (n >= NN) return;

    float acc[KD][8];
#pragma unroll
    for (int k = 0; k < KD; k++)
#pragma unroll
        for (int j = 0; j < 8; j++) acc[k][j] = 0.0f;

    int beg = d_rowptr[n], end = d_rowptr[n + 1];
    for (int i = beg; i < end; i++) {
        int s = d_ssrc[i];
        uint4 raw = *((const uint4*)(d_h1 + (size_t)s * H1D) + l);
        __half2* hh = (__half2*)&raw;
        float2 f0 = __half22float2(hh[0]), f1 = __half22float2(hh[1]);
        float2 f2 = __half22float2(hh[2]), f3 = __half22float2(hh[3]);
#pragma unroll
        for (int k = 0; k < KD; k++) {
            float wg = d_norm[k * NE + i];
            acc[k][0] = fmaf(wg, f0.x, acc[k][0]); acc[k][1] = fmaf(wg, f0.y, acc[k][1]);
            acc[k][2] = fmaf(wg, f1.x, acc[k][2]); acc[k][3] = fmaf(wg, f1.y, acc[k][3]);
            acc[k][4] = fmaf(wg, f2.x, acc[k][4]); acc[k][5] = fmaf(wg, f2.y, acc[k][5]);
            acc[k][6] = fmaf(wg, f3.x, acc[k][6]); acc[k][7] = fmaf(wg, f3.y, acc[k][7]);
        }
    }
    {
        uint4 raw = *((const uint4*)(d_h1 + (size_t)n * H1D) + l);
        __half2* hh = (__half2*)&raw;
        float2 f0 = __half22float2(hh[0]), f1 = __half22float2(hh[1]);
        float2 f2 = __half22float2(hh[2]), f3 = __half22float2(hh[3]);
#pragma unroll
        for (int k = 0; k < KD; k++) {
            float dv = d_dinv[k * NN + n];
            float wg = dv * dv;
            acc[k][0] = fmaf(wg, f0.x, acc[k][0]); acc[k][1] = fmaf(wg, f0.y, acc[k][1]);
            acc[k][2] = fmaf(wg, f1.x, acc[k][2]); acc[k][3] = fmaf(wg, f1.y, acc[k][3]);
            acc[k][4] = fmaf(wg, f2.x, acc[k][4]); acc[k][5] = fmaf(wg, f2.y, acc[k][5]);
            acc[k][6] = fmaf(wg, f3.x, acc[k][6]); acc[k][7] = fmaf(wg, f3.y, acc[k][7]);
        }
    }
    float4 b0 = ((const float4*)g1_b)[l * 2];
    float4 b1 = ((const float4*)g1_b)[l * 2 + 1];
#pragma unroll
    for (int k = 0; k < KD; k++) {
        uint32_t p0 = h2u(__floats2half2_rn(fmaxf(acc[k][0] + b0.x, 0.f), fmaxf(acc[k][1] + b0.y, 0.f)));
        uint32_t p1 = h2u(__floats2half2_rn(fmaxf(acc[k][2] + b0.z, 0.f), fmaxf(acc[k][3] + b0.w, 0.f)));
        uint32_t p2 = h2u(__floats2half2_rn(fmaxf(acc[k][4] + b1.x, 0.f), fmaxf(acc[k][5] + b1.y, 0.f)));
        uint32_t p3 = h2u(__floats2half2_rn(fmaxf(acc[k][6] + b1.z, 0.f), fmaxf(acc[k][7] + b1.w, 0.f)));
        *((uint4*)(d_z1 + ((size_t)(k * NN + n)) * H1D) + l) = make_uint4(p0, p1, p2, p3);
    }
}

// ---------------- GCN layer-2 aggregation (per-k via blockIdx.y) + mean accum ---------
__global__ void agg2_kernel(const float* __restrict__ g2_b) {
    __shared__ float sacc[H2D];
    int t = threadIdx.x;
    int k = blockIdx.y;
    if (t < H2D) sacc[t] = 0.0f;
    __syncthreads();

    int w = t >> 5, l = t & 31;
    int n = blockIdx.x * 8 + w;
    if (n < NN) {
        float a0 = 0.f, a1 = 0.f, a2 = 0.f, a3 = 0.f;
        const __half* h2k = d_h2 + (size_t)k * NN * H2D;
        const float*  nrm = d_norm + (size_t)k * NE;

        int beg = d_rowptr[n], end = d_rowptr[n + 1];
        for (int i = beg; i < end; i++) {
            int s = d_ssrc[i];
            float wg = nrm[i];
            uint2 raw = *((const uint2*)(h2k + (size_t)s * H2D) + l);
            __half2* hh = (__half2*)&raw;
            float2 f0 = __half22float2(hh[0]), f1 = __half22float2(hh[1]);
            a0 = fmaf(wg, f0.x, a0); a1 = fmaf(wg, f0.y, a1);
            a2 = fmaf(wg, f1.x, a2); a3 = fmaf(wg, f1.y, a3);
        }
        {
            float dv = d_dinv[k * NN + n];
            float wg = dv * dv;
            uint2 raw = *((const uint2*)(h2k + (size_t)n * H2D) + l);
            __half2* hh = (__half2*)&raw;
            float2 f0 = __half22float2(hh[0]), f1 = __half22float2(hh[1]);
            a0 = fmaf(wg, f0.x, a0); a1 = fmaf(wg, f0.y, a1);
            a2 = fmaf(wg, f1.x, a2); a3 = fmaf(wg, f1.y, a3);
        }
        float4 b = ((const float4*)g2_b)[l];
        atomicAdd(&sacc[l * 4 + 0], fmaxf(a0 + b.x, 0.f));
        atomicAdd(&sacc[l * 4 + 1], fmaxf(a1 + b.y, 0.f));
        atomicAdd(&sacc[l * 4 + 2], fmaxf(a2 + b.z, 0.f));
        atomicAdd(&sacc[l * 4 + 3], fmaxf(a3 + b.w, 0.f));
    }
    __syncthreads();
    if (t < H2D) atomicAdd(&d_macc[k * H2D + t], sacc[t]);
}

// ---------------- final descriptors ----------------
__global__ void final_kernel(const float* __restrict__ fc_W, const float* __restrict__ fc_b,
                             float* __restrict__ out) {
    int t = threadIdx.x;
    int k = t >> 5, o = t & 31;
    const float inv = 1.0f / (float)NN;
    float s = fc_b[o];
    for (int d = 0; d < H2D; d++) s = fmaf(d_macc[k * H2D + d] * inv, fc_W[d * ODIM + o], s);
    out[t] = s;
}

// ---------------- launch ----------------
static void* symp(const void* s) {
    void* p = nullptr;
    cudaGetSymbolAddress(&p, s);
    return p;
}

extern "C" void kernel_launch(void* const* d_in, const int* in_sizes, int n_in,
                              void* d_out, int out_size) {
    const float* X     = (const float*)d_in[0];
    const int*   ei    = (const int*)d_in[1];
    const float* Wh    = (const float*)d_in[2];
    const float* W1    = (const float*)d_in[3];
    const float* b1    = (const float*)d_in[4];
    const float* W2    = (const float*)d_in[5];
    const float* b2    = (const float*)d_in[6];
    const float* g1_W  = (const float*)d_in[7];
    const float* g1_b  = (const float*)d_in[8];
    const float* g2_W  = (const float*)d_in[9];
    const float* g2_b  = (const float*)d_in[10];
    const float* fc_W  = (const float*)d_in[11];
    const float* fc_b  = (const float*)d_in[12];

    const int* src = ei;
    const int* dst = ei + NE;

    float* out = (float*)d_out;
    float* G   = out + KD * ODIM;

    __half* p_h0  = (__half*)symp(d_h0);
    __half* p_h1  = (__half*)symp(d_h1);
    __half* p_z1  = (__half*)symp(d_z1);
    __half* p_h2  = (__half*)symp(d_h2);
    __half* p_WhT = (__half*)symp(d_WhT);
    __half* p_g1T = (__half*)symp(d_g1T);
    __half* p_g2T = (__half*)symp(d_g2T);

    const int SMF32 = NSTG * (128 * 144 + 128 * 80);   // 114688
    const int SMF16 = NSTG * (128 * 80 + 128 * 80);    // 81920
    cudaFuncSetAttribute(gemm_pipe<true>,  cudaFuncAttributeMaxDynamicSharedMemorySize, SMF32);
    cudaFuncSetAttribute(gemm_pipe<false>, cudaFuncAttributeMaxDynamicSharedMemorySize, SMF16);

    init_kernel<<<(KD * NN + 255) / 256, 256>>>();
    prep_weights<<<(DF * KPAD1 + 255) / 256, 256>>>(Wh, g1_W, g2_W);

    // 1. h0 = fp16(X @ Wh) — cp.async pipelined HMMA, fp32 A converted at fragment load
    {
        dim3 grid((NN + 127) / 128, 1);
        gemm_pipe<true><<<grid, 256, SMF32>>>(X, p_WhT, p_h0, NN, INDIM, KPAD1, DF, KPAD1 / 32);
    }

    // 1b. per-node edge-MLP projections (SIMT, fp32 out)
    pq_kernel<<<(NN + 255) / 256, 256>>>(W1);

    // 2. edge gates + degree accumulation + dst counts (fused)
    edge_gate_kernel<<<(NE + 255) / 256, 256>>>(src, dst, b1, W2, b2, G);

    // 3. dinv
    dinv_kernel<<<(KD * NN + 255) / 256, 256>>>();

    // 4. scan -> rowptr
    int nblk = (NN + 1023) / 1024;
    scanA_kernel<<<nblk, 1024>>>();
    scanB_kernel<<<1, 32>>>(nblk);
    scanC_kernel<<<(NN + 255) / 256, 256>>>();

    // 5. scatter CSR + norms
    scatter_kernel<<<(NE + 255) / 256, 256>>>(src, dst, G);

    // 6. h1 = fp16(h0 @ g1_W)
    {
        dim3 grid((NN + 127) / 128, H1D / 128);
        gemm_pipe<false><<<grid, 256, SMF16>>>(p_h0, p_g1T, p_h1, NN, DF, DF, H1D, DF / 32);
    }

    // 7. layer-1 aggregation -> z1 fp16
    agg1_kernel<<<(NN + 7) / 8, 256>>>(g1_b);

    // 8. h2 = fp16(z1 @ g2_W) (batched over K: M = K*NN)
    {
        dim3 grid((KD * NN + 127) / 128, H2D / 128);
        gemm_pipe<false><<<grid, 256, SMF16>>>(p_z1, p_g2T, p_h2, KD * NN, H1D, H1D, H2D, H1D / 32);
    }

    // 9. layer-2 aggregation + relu + mean accumulation (k = blockIdx.y for L2 locality)
    {
        dim3 grid((NN + 7) / 8, KD);
        agg2_kernel<<<grid, 256>>>(g2_b);
    }

    // 10. descriptors
    final_kernel<<<1, 128>>>(fc_W, fc_b, out);
}